// round 5
// baseline (speedup 1.0000x reference)
#include <cuda_runtime.h>
#include <cstdint>

#define DINLINE __device__ __forceinline__

static constexpr int KDIM = 12544;
static constexpr int NOUT = 168;
static constexpr int NSTG = 4;
static constexpr int A_ST  = 128 * 64;          // 8192 B per stage (128 rows x 16 tf32)
static constexpr int B_ST  = 168 * 64;          // 10752 B per stage
static constexpr int STAGE = A_ST + B_ST;       // 18944 B
static constexpr int SMEM_BYTES = NSTG * STAGE; // 75776 B

// Output segment bases (concatenated tuple, row-major each)
static constexpr int SEG_CLS = 0;
static constexpr int SEG_REG = 262144;
static constexpr int SEG_FAC = 1277952;
static constexpr int SEG_COL = 1302528;
static constexpr int SEG_MOT = 1359872;

// Scratch (device globals: sanctioned no-alloc workaround)
__device__ float g_Wt[(size_t)NOUT * KDIM];   // [n][k], tf32 RNA-rounded
__device__ float g_acc[(size_t)8192 * NOUT];  // fp32 accumulator [row][n]

// ---------------- PTX helpers (base sm_103 ISA only) ----------------
DINLINE uint32_t smem_u32(const void* p) {
    uint32_t a;
    asm("{ .reg .u64 t; cvta.to.shared.u64 t, %1; cvt.u32.u64 %0, t; }" : "=r"(a) : "l"(p));
    return a;
}
DINLINE void ldsm4(uint32_t* r, uint32_t a) {
    asm volatile("ldmatrix.sync.aligned.m8n8.x4.shared.b16 {%0,%1,%2,%3}, [%4];"
                 : "=r"(r[0]), "=r"(r[1]), "=r"(r[2]), "=r"(r[3]) : "r"(a));
}
DINLINE void ldsm2(uint32_t* r, uint32_t a) {
    asm volatile("ldmatrix.sync.aligned.m8n8.x2.shared.b16 {%0,%1}, [%2];"
                 : "=r"(r[0]), "=r"(r[1]) : "r"(a));
}
DINLINE void mma8(float* d, const uint32_t* a, uint32_t b0, uint32_t b1) {
    asm volatile(
        "mma.sync.aligned.m16n8k8.row.col.f32.tf32.tf32.f32 "
        "{%0,%1,%2,%3}, {%4,%5,%6,%7}, {%8,%9}, {%0,%1,%2,%3};"
        : "+f"(d[0]), "+f"(d[1]), "+f"(d[2]), "+f"(d[3])
        : "r"(a[0]), "r"(a[1]), "r"(a[2]), "r"(a[3]), "r"(b0), "r"(b1));
}
DINLINE void cp16(uint32_t s, const void* g) {
    asm volatile("cp.async.cg.shared.global [%0], [%1], 16;" :: "r"(s), "l"(g));
}
DINLINE void cp_commit() { asm volatile("cp.async.commit_group;" ::: "memory"); }
DINLINE void cp_wait2()  { asm volatile("cp.async.wait_group 2;" ::: "memory"); }
DINLINE void redadd(float* p, float v) {
    asm volatile("red.global.add.f32 [%0], %1;" :: "l"(p), "f"(v) : "memory");
}
// swizzled byte offset within a stage tile: row stride 64B, 4 x 16B chunks
DINLINE uint32_t swz(int row, int c) {
    return (uint32_t)row * 64u + (uint32_t)((c ^ ((row >> 1) & 3)) << 4);
}

// ---------------- Kernel 1: transpose+concat W into g_Wt (tf32 RNA) ----------------
__global__ void prep_kernel(const float* __restrict__ Wc, const float* __restrict__ Wr,
                            const float* __restrict__ Wf, const float* __restrict__ Wco,
                            const float* __restrict__ Wm) {
    __shared__ float tile[32][33];
    int kt = blockIdx.x, nt = blockIdx.y;
    int tx = threadIdx.x, ty = threadIdx.y;  // 32 x 8
#pragma unroll
    for (int dy = 0; dy < 4; dy++) {
        int k = kt * 32 + ty + dy * 8;
        int n = nt * 32 + tx;
        float v = 0.f;
        if (n < NOUT) {
            const float* W; int dim, nl;
            if (n < 32)       { W = Wc;  dim = 32;  nl = n; }
            else if (n < 156) { W = Wr;  dim = 124; nl = n - 32; }
            else if (n < 159) { W = Wf;  dim = 3;   nl = n - 156; }
            else if (n < 166) { W = Wco; dim = 7;   nl = n - 159; }
            else              { W = Wm;  dim = 2;   nl = n - 166; }
            v = W[(size_t)k * dim + nl];
        }
        tile[ty + dy * 8][tx] = v;
    }
    __syncthreads();
#pragma unroll
    for (int dy = 0; dy < 4; dy++) {
        int n = nt * 32 + ty + dy * 8;
        int k = kt * 32 + tx;
        if (n < NOUT) {
            float v = tile[tx][ty + dy * 8];
            // RNA round to tf32 (HMMA reads top 19 bits; +0x1000 = round-to-nearest)
            g_Wt[(size_t)n * KDIM + k] = __uint_as_float(__float_as_uint(v) + 0x1000u);
        }
    }
}

// ---------------- Kernel 2: zero the accumulator ----------------
__global__ void zero_acc_kernel() {
    float4* p = reinterpret_cast<float4*>(g_acc);
    const int total = 8192 * NOUT / 4;  // 344064
    for (int i = blockIdx.x * blockDim.x + threadIdx.x; i < total; i += gridDim.x * blockDim.x)
        p[i] = make_float4(0.f, 0.f, 0.f, 0.f);
}

// ---------------- Kernel 3: tf32 mma.sync GEMM, balanced K-split, red-accumulate ----------------
__global__ void __launch_bounds__(128)
gemm_kernel(const float* __restrict__ x) {
    extern __shared__ char smem[];
    const uint32_t sbase = smem_u32(smem);
    const int tid = threadIdx.x;
    const int wid = tid >> 5, l = tid & 31;
    const int wm = wid >> 1, wn = wid & 1;
    const int n0w = wn * 88;
    const bool extra = (wn == 0);      // wn0: 11 n8-tiles, wn1: 10

    // Work item decode: 296 items = 40 mtiles x 5 splits + 24 mtiles x 4 splits.
    int it = blockIdx.x, mtile, s, ns;
    if (it < 200) { mtile = it / 5; s = it - mtile * 5; ns = 5; }
    else { int j = it - 200; mtile = 40 + (j >> 2); s = j & 3; ns = 4; }
    const int TOTU = KDIM / 16;                       // 784 stage-units
    int ubase = TOTU / ns, urem = TOTU - ubase * ns;
    int u0 = s * ubase + (s < urem ? s : urem);
    int ucnt = ubase + (s < urem ? 1 : 0);
    const int k0 = u0 * 16;
    const int nstages = ucnt;                         // stages of k=16
    const int row0 = mtile * 128;

    // ---- cp.async stage loader ----
    auto issue = [&](int st) {
        if (st >= nstages) return;
        const uint32_t Ast = sbase + (st & (NSTG - 1)) * STAGE;
        const uint32_t Bst = Ast + A_ST;
        const int kg = k0 + st * 16;
#pragma unroll
        for (int i = 0; i < 4; i++) {
            int q = tid + 128 * i;            // 512 A chunks
            int row = q >> 2, c = q & 3;
            cp16(Ast + swz(row, c), x + (size_t)(row0 + row) * KDIM + kg + c * 4);
        }
#pragma unroll
        for (int i = 0; i < 6; i++) {
            int q = tid + 128 * i;            // 672 B chunks
            if (q < 672) {
                int n = q >> 2, c = q & 3;
                cp16(Bst + swz(n, c), g_Wt + (size_t)n * KDIM + kg + c * 4);
            }
        }
    };

    float acc[4][11][4];
#pragma unroll
    for (int i = 0; i < 4; i++)
#pragma unroll
        for (int j = 0; j < 11; j++)
#pragma unroll
            for (int k = 0; k < 4; k++) acc[i][j][k] = 0.f;

    // prologue: 3 stages in flight
    issue(0); cp_commit();
    issue(1); cp_commit();
    issue(2); cp_commit();

    for (int st = 0; st < nstages; st++) {
        cp_wait2();
        __syncthreads();
        issue(st + NSTG - 1); cp_commit();

        const uint32_t Ast = sbase + (st & (NSTG - 1)) * STAGE;
        const uint32_t Bst = Ast + A_ST;
#pragma unroll
        for (int mu = 0; mu < 2; mu++) {     // two k8 micro-steps per stage
            uint32_t b[20], bx[2];
            const int cB = 2 * mu + ((l >> 3) & 1);
#pragma unroll
            for (int g2 = 0; g2 < 5; g2++) {
                int nrow = n0w + 8 * (2 * g2 + ((l >> 4) & 1)) + (l & 7);
                ldsm4(&b[g2 * 4], Bst + swz(nrow, cB));
            }
            if (extra) {
                int nrow = n0w + 80 + (l & 7);
                ldsm2(bx, Bst + swz(nrow, cB));
            }
#pragma unroll
            for (int mt = 0; mt < 4; mt++) {
                int mrow = wm * 64 + mt * 16 + ((l >> 3) & 1) * 8 + (l & 7);
                int cA = 2 * mu + (l >> 4);
                uint32_t a[4];
                ldsm4(a, Ast + swz(mrow, cA));
#pragma unroll
                for (int g2 = 0; g2 < 5; g2++) {
                    mma8(acc[mt][2 * g2 + 0], a, b[4 * g2 + 0], b[4 * g2 + 1]);
                    mma8(acc[mt][2 * g2 + 1], a, b[4 * g2 + 2], b[4 * g2 + 3]);
                }
                if (extra) mma8(acc[mt][10], a, bx[0], bx[1]);
            }
        }
    }

    // ---- epilogue: red.global.add into g_acc ----
    const int ntiles = 11 - wn;
    const int rbase = row0 + wm * 64 + (l >> 2);
#pragma unroll
    for (int mt = 0; mt < 4; mt++) {
#pragma unroll
        for (int nt = 0; nt < 11; nt++) {
            if (nt < ntiles) {
                int r = rbase + mt * 16;
                int cn = n0w + nt * 8 + (l & 3) * 2;
                float* p = g_acc + (size_t)r * NOUT + cn;
                redadd(p,                acc[mt][nt][0]);
                redadd(p + 1,            acc[mt][nt][1]);
                redadd(p + 8 * NOUT,     acc[mt][nt][2]);
                redadd(p + 8 * NOUT + 1, acc[mt][nt][3]);
            }
        }
    }
}

// ---------------- Kernel 4: bias + scatter to output segments ----------------
__global__ void final_kernel(float* __restrict__ out,
                             const float* __restrict__ bc, const float* __restrict__ br,
                             const float* __restrict__ bf, const float* __restrict__ bco,
                             const float* __restrict__ bm) {
    int idx = blockIdx.x * blockDim.x + threadIdx.x;
    if (idx >= 8192 * NOUT) return;
    int row = idx / NOUT, c = idx - row * NOUT;
    float v = g_acc[idx];
    size_t a; float b;
    if (c < 32)       { a = SEG_CLS + (size_t)row * 32 + c;          b = bc[c]; }
    else if (c < 156) { a = SEG_REG + (size_t)row * 124 + (c - 32);  b = br[c - 32]; }
    else if (c < 159) { a = SEG_FAC + (size_t)row * 3 + (c - 156);   b = bf[c - 156]; }
    else if (c < 166) { a = SEG_COL + (size_t)row * 7 + (c - 159);   b = bco[c - 159]; }
    else              { a = SEG_MOT + (size_t)row * 2 + (c - 166);   b = bm[c - 166]; }
    out[a] = v + b;
}

// ---------------- Launch ----------------
extern "C" void kernel_launch(void* const* d_in, const int* in_sizes, int n_in,
                              void* d_out, int out_size) {
    const float* x   = (const float*)d_in[0];
    const float* Wc  = (const float*)d_in[1];
    const float* bc  = (const float*)d_in[2];
    const float* Wr  = (const float*)d_in[3];
    const float* br  = (const float*)d_in[4];
    const float* Wf  = (const float*)d_in[5];
    const float* bf  = (const float*)d_in[6];
    const float* Wco = (const float*)d_in[7];
    const float* bco = (const float*)d_in[8];
    const float* Wm  = (const float*)d_in[9];
    const float* bm  = (const float*)d_in[10];
    float* out = (float*)d_out;

    cudaFuncSetAttribute(gemm_kernel, cudaFuncAttributeMaxDynamicSharedMemorySize, SMEM_BYTES);

    prep_kernel<<<dim3(KDIM / 32, 6), dim3(32, 8)>>>(Wc, Wr, Wf, Wco, Wm);
    zero_acc_kernel<<<336, 256>>>();
    gemm_kernel<<<296, 128, SMEM_BYTES>>>(x);
    final_kernel<<<(8192 * NOUT + 255) / 256, 256>>>(out, bc, br, bf, bco, bm);
}

// round 6
// speedup vs baseline: 1.6536x; 1.6536x over previous
#include <cuda_runtime.h>
#include <cuda_fp16.h>
#include <cstdint>

#define DINLINE __device__ __forceinline__

static constexpr int KDIM = 12544;
static constexpr int NOUT = 168;
static constexpr int NSTG = 4;
static constexpr int A_ST  = 128 * 64;          // 128 rows x 32 fp16 = 8192 B
static constexpr int B_ST  = 168 * 64;          // 168 rows x 32 fp16 = 10752 B
static constexpr int STAGE = A_ST + B_ST;       // 18944 B
static constexpr int SMEM_BYTES = NSTG * STAGE; // 75776 B (2 CTAs/SM fit)

// Output segment bases (concatenated tuple, row-major each)
static constexpr int SEG_CLS = 0;
static constexpr int SEG_REG = 262144;
static constexpr int SEG_FAC = 1277952;
static constexpr int SEG_COL = 1302528;
static constexpr int SEG_MOT = 1359872;

// Scratch (device globals: sanctioned no-alloc workaround)
__device__ __half g_Wh[(size_t)NOUT * KDIM];  // [n][k], fp16 RN
__device__ float  g_acc[(size_t)8192 * NOUT]; // fp32 accumulator [row][n]

// ---------------- PTX helpers (base sm_103 ISA only) ----------------
DINLINE uint32_t smem_u32(const void* p) {
    uint32_t a;
    asm("{ .reg .u64 t; cvta.to.shared.u64 t, %1; cvt.u32.u64 %0, t; }" : "=r"(a) : "l"(p));
    return a;
}
DINLINE void ldsm4(uint32_t* r, uint32_t a) {
    asm volatile("ldmatrix.sync.aligned.m8n8.x4.shared.b16 {%0,%1,%2,%3}, [%4];"
                 : "=r"(r[0]), "=r"(r[1]), "=r"(r[2]), "=r"(r[3]) : "r"(a));
}
DINLINE void ldsm2(uint32_t* r, uint32_t a) {
    asm volatile("ldmatrix.sync.aligned.m8n8.x2.shared.b16 {%0,%1}, [%2];"
                 : "=r"(r[0]), "=r"(r[1]) : "r"(a));
}
DINLINE void mma16(float* d, const uint32_t* a, uint32_t b0, uint32_t b1) {
    asm volatile(
        "mma.sync.aligned.m16n8k16.row.col.f32.f16.f16.f32 "
        "{%0,%1,%2,%3}, {%4,%5,%6,%7}, {%8,%9}, {%0,%1,%2,%3};"
        : "+f"(d[0]), "+f"(d[1]), "+f"(d[2]), "+f"(d[3])
        : "r"(a[0]), "r"(a[1]), "r"(a[2]), "r"(a[3]), "r"(b0), "r"(b1));
}
DINLINE void cp16(uint32_t s, const void* g) {
    asm volatile("cp.async.cg.shared.global [%0], [%1], 16;" :: "r"(s), "l"(g));
}
DINLINE void cp_commit() { asm volatile("cp.async.commit_group;" ::: "memory"); }
DINLINE void cp_wait2()  { asm volatile("cp.async.wait_group 2;" ::: "memory"); }
DINLINE void redadd(float* p, float v) {
    asm volatile("red.global.add.f32 [%0], %1;" :: "l"(p), "f"(v) : "memory");
}
// swizzled byte offset within a stage tile: row stride 64B, 4 x 16B chunks
DINLINE uint32_t swz(int row, int c) {
    return (uint32_t)row * 64u + (uint32_t)((c ^ ((row >> 1) & 3)) << 4);
}
DINLINE uint32_t h2u(__half2 h) {
    uint32_t u; __builtin_memcpy(&u, &h, 4); return u;
}

// ---------------- Kernel 1: transpose+concat W into g_Wh (fp16 RN) ----------------
__global__ void prep_kernel(const float* __restrict__ Wc, const float* __restrict__ Wr,
                            const float* __restrict__ Wf, const float* __restrict__ Wco,
                            const float* __restrict__ Wm) {
    __shared__ float tile[32][33];
    int kt = blockIdx.x, nt = blockIdx.y;
    int tx = threadIdx.x, ty = threadIdx.y;  // 32 x 8
#pragma unroll
    for (int dy = 0; dy < 4; dy++) {
        int k = kt * 32 + ty + dy * 8;
        int n = nt * 32 + tx;
        float v = 0.f;
        if (n < NOUT) {
            const float* W; int dim, nl;
            if (n < 32)       { W = Wc;  dim = 32;  nl = n; }
            else if (n < 156) { W = Wr;  dim = 124; nl = n - 32; }
            else if (n < 159) { W = Wf;  dim = 3;   nl = n - 156; }
            else if (n < 166) { W = Wco; dim = 7;   nl = n - 159; }
            else              { W = Wm;  dim = 2;   nl = n - 166; }
            v = W[(size_t)k * dim + nl];
        }
        tile[ty + dy * 8][tx] = v;
    }
    __syncthreads();
#pragma unroll
    for (int dy = 0; dy < 4; dy++) {
        int n = nt * 32 + ty + dy * 8;
        int k = kt * 32 + tx;
        if (n < NOUT)
            g_Wh[(size_t)n * KDIM + k] = __float2half_rn(tile[tx][ty + dy * 8]);
    }
}

// ---------------- Kernel 2: zero the accumulator ----------------
__global__ void zero_acc_kernel() {
    float4* p = reinterpret_cast<float4*>(g_acc);
    const int total = 8192 * NOUT / 4;  // 344064
    for (int i = blockIdx.x * blockDim.x + threadIdx.x; i < total; i += gridDim.x * blockDim.x)
        p[i] = make_float4(0.f, 0.f, 0.f, 0.f);
}

// ---------------- Kernel 3: fp16 mma.sync GEMM, balanced K-split, red-accumulate ----------------
__global__ void __launch_bounds__(128, 2)
gemm_kernel(const float* __restrict__ x) {
    extern __shared__ char smem[];
    const uint32_t sbase = smem_u32(smem);
    const int tid = threadIdx.x;
    const int wid = tid >> 5, l = tid & 31;
    const int wm = wid >> 1, wn = wid & 1;
    const int n0w = wn * 88;
    const bool extra = (wn == 0);      // wn0: 11 n8-tiles, wn1: 10

    // Work item decode: 296 items = 40 mtiles x 5 splits + 24 mtiles x 4 splits.
    int it = blockIdx.x, mtile, s, ns;
    if (it < 200) { mtile = it / 5; s = it - mtile * 5; ns = 5; }
    else { int j = it - 200; mtile = 40 + (j >> 2); s = j & 3; ns = 4; }
    const int TOTU = KDIM / 32;                       // 392 stage-units of k=32
    int ubase = TOTU / ns, urem = TOTU - ubase * ns;
    int u0 = s * ubase + (s < urem ? s : urem);
    int nstages = ubase + (s < urem ? 1 : 0);
    const int k0 = u0 * 32;
    const int row0 = mtile * 128;

    // ---- B stage loader (cp.async, fp16 direct) ----
    auto issueB = [&](int st) {
        if (st >= nstages) return;
        const uint32_t Bst = sbase + (st & (NSTG - 1)) * STAGE + A_ST;
        const int kg = k0 + st * 32;
#pragma unroll
        for (int i = 0; i < 6; i++) {
            int q = tid + 128 * i;            // 672 chunks of 16B (8 halves)
            if (q < 672) {
                int n = q >> 2, c = q & 3;
                cp16(Bst + swz(n, c), g_Wh + (size_t)n * KDIM + kg + c * 8);
            }
        }
    };
    // ---- A loader: fp32 LDG into registers (coalesced: 8 lanes per row) ----
    auto ldgA = [&](int st, float4* va) {
        const int kg = k0 + st * 32;
        const int c8 = tid & 7;            // float4 column within row (32 floats)
        const int rb = tid >> 3;
#pragma unroll
        for (int i = 0; i < 8; i++) {
            int r = rb + 16 * i;
            va[i] = *reinterpret_cast<const float4*>(x + (size_t)(row0 + r) * KDIM + kg + c8 * 4);
        }
    };
    // ---- A store: cvt fp32->fp16, swizzled STS.64 ----
    auto stsA = [&](int st, const float4* va) {
        const uint32_t Ast = sbase + (st & (NSTG - 1)) * STAGE;
        const int c8 = tid & 7;
        const int rb = tid >> 3;
        const uint32_t sub = (uint32_t)((c8 & 1) << 3);
        const int cc = c8 >> 1;
#pragma unroll
        for (int i = 0; i < 8; i++) {
            int r = rb + 16 * i;
            uint2 h;
            h.x = h2u(__floats2half2_rn(va[i].x, va[i].y));
            h.y = h2u(__floats2half2_rn(va[i].z, va[i].w));
            *reinterpret_cast<uint2*>(smem + (Ast - sbase) + swz(r, cc) + sub) = h;
        }
    };

    float acc[4][11][4];
#pragma unroll
    for (int i = 0; i < 4; i++)
#pragma unroll
        for (int j = 0; j < 11; j++)
#pragma unroll
            for (int k = 0; k < 4; k++) acc[i][j][k] = 0.f;

    float4 va[8];
    ldgA(0, va);
    issueB(0); cp_commit();
    issueB(1); cp_commit();
    issueB(2); cp_commit();

#pragma unroll 1
    for (int st = 0; st < nstages; st++) {
        cp_wait2();
        __syncthreads();                    // stage st-4 fully consumed; B(st) visible
        stsA(st, va);
        issueB(st + 3); cp_commit();
        if (st + 1 < nstages) ldgA(st + 1, va);   // prefetch next A (overlaps compute)
        __syncthreads();                    // A(st) visible

        const uint32_t Ast = sbase + (st & (NSTG - 1)) * STAGE;
        const uint32_t Bst = Ast + A_ST;
#pragma unroll
        for (int ks = 0; ks < 2; ks++) {    // two k16 micro-steps per k32 stage
            uint32_t b[20], bx[2];
            const int cB = 2 * ks + ((l >> 3) & 1);
#pragma unroll
            for (int g2 = 0; g2 < 5; g2++) {
                int nrow = n0w + 8 * (2 * g2 + ((l >> 4) & 1)) + (l & 7);
                ldsm4(&b[g2 * 4], Bst + swz(nrow, cB));
            }
            if (extra) {
                int nrow = n0w + 80 + (l & 7);
                ldsm2(bx, Bst + swz(nrow, cB));
            }
#pragma unroll
            for (int mt = 0; mt < 4; mt++) {
                int mrow = wm * 64 + mt * 16 + (l & 15);
                int cA = 2 * ks + (l >> 4);
                uint32_t a[4];
                ldsm4(a, Ast + swz(mrow, cA));
#pragma unroll
                for (int g2 = 0; g2 < 5; g2++) {
                    mma16(acc[mt][2 * g2 + 0], a, b[4 * g2 + 0], b[4 * g2 + 1]);
                    mma16(acc[mt][2 * g2 + 1], a, b[4 * g2 + 2], b[4 * g2 + 3]);
                }
                if (extra) mma16(acc[mt][10], a, bx[0], bx[1]);
            }
        }
    }

    // ---- epilogue: red.global.add into g_acc ----
    const int ntiles = 11 - wn;
    const int rbase = row0 + wm * 64 + (l >> 2);
#pragma unroll
    for (int mt = 0; mt < 4; mt++) {
#pragma unroll
        for (int nt = 0; nt < 11; nt++) {
            if (nt < ntiles) {
                int r = rbase + mt * 16;
                int cn = n0w + nt * 8 + (l & 3) * 2;
                float* p = g_acc + (size_t)r * NOUT + cn;
                redadd(p,                acc[mt][nt][0]);
                redadd(p + 1,            acc[mt][nt][1]);
                redadd(p + 8 * NOUT,     acc[mt][nt][2]);
                redadd(p + 8 * NOUT + 1, acc[mt][nt][3]);
            }
        }
    }
}

// ---------------- Kernel 4: bias + scatter to output segments ----------------
__global__ void final_kernel(float* __restrict__ out,
                             const float* __restrict__ bc, const float* __restrict__ br,
                             const float* __restrict__ bf, const float* __restrict__ bco,
                             const float* __restrict__ bm) {
    int idx = blockIdx.x * blockDim.x + threadIdx.x;
    if (idx >= 8192 * NOUT) return;
    int row = idx / NOUT, c = idx - row * NOUT;
    float v = g_acc[idx];
    size_t a; float b;
    if (c < 32)       { a = SEG_CLS + (size_t)row * 32 + c;          b = bc[c]; }
    else if (c < 156) { a = SEG_REG + (size_t)row * 124 + (c - 32);  b = br[c - 32]; }
    else if (c < 159) { a = SEG_FAC + (size_t)row * 3 + (c - 156);   b = bf[c - 156]; }
    else if (c < 166) { a = SEG_COL + (size_t)row * 7 + (c - 159);   b = bco[c - 159]; }
    else              { a = SEG_MOT + (size_t)row * 2 + (c - 166);   b = bm[c - 166]; }
    out[a] = v + b;
}

// ---------------- Launch ----------------
extern "C" void kernel_launch(void* const* d_in, const int* in_sizes, int n_in,
                              void* d_out, int out_size) {
    const float* x   = (const float*)d_in[0];
    const float* Wc  = (const float*)d_in[1];
    const float* bc  = (const float*)d_in[2];
    const float* Wr  = (const float*)d_in[3];
    const float* br  = (const float*)d_in[4];
    const float* Wf  = (const float*)d_in[5];
    const float* bf  = (const float*)d_in[6];
    const float* Wco = (const float*)d_in[7];
    const float* bco = (const float*)d_in[8];
    const float* Wm  = (const float*)d_in[9];
    const float* bm  = (const float*)d_in[10];
    float* out = (float*)d_out;

    cudaFuncSetAttribute(gemm_kernel, cudaFuncAttributeMaxDynamicSharedMemorySize, SMEM_BYTES);

    prep_kernel<<<dim3(KDIM / 32, 6), dim3(32, 8)>>>(Wc, Wr, Wf, Wco, Wm);
    zero_acc_kernel<<<336, 256>>>();
    gemm_kernel<<<296, 128, SMEM_BYTES>>>(x);
    final_kernel<<<(8192 * NOUT + 255) / 256, 256>>>(out, bc, br, bf, bco, bm);
}